// round 12
// baseline (speedup 1.0000x reference)
#include <cuda_runtime.h>
#include <cuda_bf16.h>
#include <cstdint>

// ---------------------------------------------------------------------------
// 2-layer LSTM, B=64, S=512, I=64, H=512, fc head on final h1.
// 64 persistent CTAs x 256 threads. wg0 = layer0 (K=576), wg1 = layer1
// (K=1024). R12: A-fragments load DIRECTLY from L2 via __ldcg with a 4-deep
// register prefetch ring (16 LDGs in flight/warp) -> no cp.async, no A-SMEM,
// no per-chunk bars (2 bars/phase total). B (weights, bf16x2) stays in SMEM.
// Sync = R7's aggregated release counters (proven best):
//   g_c0 == 64*(p+2) after all wg0 finish phase p (init post included).
//   g_c1 == 64*(p+1) after all wg1 finish phase p (equalizer post included).
// h rings 4 deep. Cell state in registers. Exit protocol resets counters.
// ---------------------------------------------------------------------------

#define NC    64
#define NTHR  256
#define BSZ   64
#define SEQ   512

#define WSTR  40                      // sW padded words per kp-row
#define KP0   288                     // layer0 K/2
#define KP1   512                     // layer1 K/2
#define KK0   36                      // wg0 k16 steps (576/16)
#define KK1   64                      // wg1 k16 steps
#define SPLIT0 4                      // wg0: kk<4 from x, else h0
#define SPLIT1 32                     // wg1: kk<32 from h0, else h1

#define SW0_OFF   0
#define SW1_OFF   (KP0*WSTR)
#define SBIAS_OFF (SW1_OFF + KP1*WSTR)        // 32000
#define SMEM_WORDS (SBIAS_OFF + 64)
#define SMEM_BYTES (SMEM_WORDS*4)             // 128256

// persistent state (device globals; allocation forbidden)
__device__ uint32_t g_xw[SEQ*32*BSZ];     // [t][kp<32][b] bf16x2
__device__ uint32_t g_h0w[4][256*BSZ];    // 4-deep ring [kp][b]
__device__ uint32_t g_h1w[4][256*BSZ];
__device__ unsigned g_c0;                 // wg0 phase counter
__device__ unsigned g_c1;                 // wg1 phase counter
__device__ unsigned g_done;               // exit protocol

__device__ __forceinline__ uint32_t packbf2(float lo, float hi) {
    uint32_t r;
    asm("cvt.rn.bf16x2.f32 %0, %1, %2;" : "=r"(r) : "f"(hi), "f"(lo));
    return r;
}

__device__ __forceinline__ void mma16(float (&d)[4],
                                      uint32_t a0, uint32_t a1, uint32_t a2, uint32_t a3,
                                      uint32_t b0, uint32_t b1) {
    asm volatile(
        "mma.sync.aligned.m16n8k16.row.col.f32.bf16.bf16.f32 "
        "{%0,%1,%2,%3}, {%4,%5,%6,%7}, {%8,%9}, {%0,%1,%2,%3};"
        : "+f"(d[0]), "+f"(d[1]), "+f"(d[2]), "+f"(d[3])
        : "r"(a0), "r"(a1), "r"(a2), "r"(a3), "r"(b0), "r"(b1));
}

__device__ __forceinline__ float fast_tanh(float x) {
    float r;
    asm("tanh.approx.f32 %0, %1;" : "=f"(r) : "f"(x));
    return r;
}
__device__ __forceinline__ float sigm(float x) {
    return 0.5f * fast_tanh(0.5f * x) + 0.5f;
}

#define BAR_WG(id)  asm volatile("bar.sync %0, 128;" :: "r"(id) : "memory")

__device__ __forceinline__ uint32_t ldcg_u(const uint32_t* p) {
    uint32_t v;
    asm volatile("ld.global.cg.u32 %0, [%1];" : "=r"(v) : "l"(p));
    return v;
}
__device__ __forceinline__ unsigned ldacq(const unsigned* p) {
    unsigned v;
    asm volatile("ld.acquire.gpu.global.u32 %0, [%1];" : "=r"(v) : "l"(p));
    return v;
}
__device__ __forceinline__ void redrel(unsigned* p) {
    asm volatile("red.release.gpu.global.add.u32 [%0], %1;" :: "l"(p), "r"(1u) : "memory");
}

// spin until *ctr >= tgt (single hot word, acquire loads, warp-coalesced)
__device__ __forceinline__ void wait_ge(unsigned* ctr, unsigned tgt) {
    while ((int)(ldacq(ctr) - tgt) < 0) { }
}
// wg-wide post: bar orders all wg stores before the single release-add
__device__ __forceinline__ void wg_post(unsigned* ctr, int tid7, int barid) {
    BAR_WG(barid);
    if (tid7 == 0) redrel(ctr);
}

// load one k16-step's A fragment (4 independent LDG.32, L2-resident data)
__device__ __forceinline__ void ldkk(uint32_t* d, int kk,
                                     const uint32_t* __restrict__ pA,
                                     const uint32_t* __restrict__ pB,
                                     int splitKK, int aoff) {
    const uint32_t* s = ((kk < splitKK) ? pA + kk * 512
                                        : pB + (kk - splitKK) * 512) + aoff;
    d[0] = ldcg_u(s);
    d[1] = ldcg_u(s + 8);
    d[2] = ldcg_u(s + 256);
    d[3] = ldcg_u(s + 264);
}

__global__ void __launch_bounds__(NTHR, 1)
lstm_persist(const float* __restrict__ W0, const float* __restrict__ b0,
             const float* __restrict__ W1, const float* __restrict__ b1,
             const float* __restrict__ Wfc, const float* __restrict__ bfc,
             float* __restrict__ out) {
    extern __shared__ uint32_t sm[];
    float* sBias = (float*)(sm + SBIAS_OFF);

    const int cta  = blockIdx.x;
    const int tid  = threadIdx.x;
    const int n0   = cta * 8;
    const int lane = tid & 31, wrp = tid >> 5;
    const int wrp4 = wrp & 3;
    const int wl   = wrp >> 2;                 // 0 = layer0, 1 = layer1
    const int g    = lane >> 2, t4 = lane & 3;
    const int rowa = wrp4 * 16 + g;
    const int aoff = t4 * BSZ + rowa;          // word offset within a k16 row-block

    const int tid7 = tid & 127;
    const int barid = 1 + wl;
    const uint32_t* sWl = sm + (wl ? SW1_OFF : SW0_OFF);
    const int biasOff = wl * 32;
    const int kpIdx = cta * 4 + t4;

    // ---- prologue: zero slot-3 h rings (h(-1) reads) ----
    for (int e = cta * NTHR + tid; e < 256 * BSZ; e += NC * NTHR) {
        g_h0w[3][e] = 0u;
        g_h1w[3][e] = 0u;
    }

    // ---- prologue: weights -> SMEM as bf16x2 ----
    for (int e = tid; e < KP0 * 32; e += NTHR) {
        int kp = e >> 5, c = e & 31;
        int q = c >> 3, j = c & 7;
        const float* w = W0 + (2 * kp) * 2048 + q * 512 + n0 + j;
        sm[SW0_OFF + kp * WSTR + c] = packbf2(w[0], w[2048]);
    }
    for (int e = tid; e < KP1 * 32; e += NTHR) {
        int kp = e >> 5, c = e & 31;
        int q = c >> 3, j = c & 7;
        const float* w = W1 + (2 * kp) * 2048 + q * 512 + n0 + j;
        sm[SW1_OFF + kp * WSTR + c] = packbf2(w[0], w[2048]);
    }
    if (tid < 64) {
        int l = tid >> 5, c = tid & 31;
        int q = c >> 3, j = c & 7;
        sBias[tid] = (l ? b1 : b0)[q * 512 + n0 + j];
    }

    __syncthreads();
    if (tid == 0) redrel(&g_c0);        // init post (zeros + weights visible)

    float creg[4] = {0.f, 0.f, 0.f, 0.f};
    float accb[4][2];
#pragma unroll
    for (int q = 0; q < 4; ++q) {
        accb[q][0] = sBias[biasOff + q * 8 + 2 * t4];
        accb[q][1] = sBias[biasOff + q * 8 + 2 * t4 + 1];
    }

    if (wl == 0) {
        // =============== layer 0: phases p = 0..511, computes t=p ===========
        for (int p = 0; p < SEQ; ++p) {
            const uint32_t* pX = g_xw + p * (32 * BSZ);
            const uint32_t* pH = g_h0w[(p + 3) & 3];            // h0(p-1)

            // prefetch kk=0..3: all x rows, NO dependency -> before the wait
            uint32_t abuf[4][4];
#pragma unroll
            for (int i = 0; i < 4; ++i) ldkk(abuf[i], i, pX, pH, SPLIT0, aoff);

            wait_ge(&g_c0, 64u * (p + 1));             // h0(p-1) ready (all)
            if (p >= 2)
                wait_ge(&g_c1, 64u * (p - 2));         // ring back-pressure

            float acc[4][4];
#pragma unroll
            for (int q = 0; q < 4; ++q) {
                acc[q][0] = accb[q][0]; acc[q][1] = accb[q][1];
                acc[q][2] = accb[q][0]; acc[q][3] = accb[q][1];
            }

#pragma unroll 4
            for (int kk = 0; kk < KK0; ++kk) {
                uint32_t a0 = abuf[kk & 3][0], a1 = abuf[kk & 3][1];
                uint32_t a2 = abuf[kk & 3][2], a3 = abuf[kk & 3][3];
                if (kk + 4 < KK0)
                    ldkk(abuf[kk & 3], kk + 4, pX, pH, SPLIT0, aoff);
                const uint32_t* bp = sWl + (kk * 8 + t4) * WSTR + g;
#pragma unroll
                for (int q = 0; q < 4; ++q)
                    mma16(acc[q], a0, a1, a2, a3, bp[q * 8], bp[4 * WSTR + q * 8]);
            }

            uint32_t* hw = g_h0w[p & 3];
            float hv[4];
#pragma unroll
            for (int pr = 0; pr < 4; ++pr) {
                float cn2 = sigm(acc[1][pr]) * creg[pr]
                          + sigm(acc[0][pr]) * fast_tanh(acc[2][pr]);
                creg[pr] = cn2;
                hv[pr] = sigm(acc[3][pr]) * fast_tanh(cn2);
            }
            __stcg(&hw[kpIdx * BSZ + rowa],     packbf2(hv[0], hv[1]));
            __stcg(&hw[kpIdx * BSZ + rowa + 8], packbf2(hv[2], hv[3]));
            wg_post(&g_c0, tid7, barid);               // g_c0 -> 64*(p+2)
        }

        // epilogue: cta0 wg0 computes fc after all wg1s finish phase 512
        if (cta == 0) {
            wait_ge(&g_c1, 64u * (SEQ + 1));
            if (tid7 < BSZ) {
                const uint32_t* h = g_h1w[(SEQ - 1) & 3];
                float s0 = 0.f, s1 = 0.f;
#pragma unroll 4
                for (int kp = 0; kp < 256; ++kp) {
                    uint32_t w = __ldcg(&h[kp * BSZ + tid7]);
                    float lo = __bfloat162float(__ushort_as_bfloat16((unsigned short)(w & 0xFFFF)));
                    float hi = __bfloat162float(__ushort_as_bfloat16((unsigned short)(w >> 16)));
                    s0 += lo * Wfc[2 * kp];
                    s1 += hi * Wfc[2 * kp + 1];
                }
                out[tid7] = s0 + s1 + bfc[0];
            }
        }
    } else {
        // =============== layer 1: phases p = 1..512, computes t=p-1 =========
        wg_post(&g_c1, tid7, barid);                   // equalizer ("phase 0")
        for (int p = 1; p <= SEQ; ++p) {
            const uint32_t* pH0 = g_h0w[(p + 3) & 3];   // h0(p-1)
            const uint32_t* pH1 = g_h1w[(p + 2) & 3];   // h1(p-2)

            wait_ge(&g_c0, 64u * (p + 1));              // h0(p-1) ready (all)

            uint32_t abuf[4][4];
#pragma unroll
            for (int i = 0; i < 4; ++i) ldkk(abuf[i], i, pH0, pH1, SPLIT1, aoff);

            float acc[4][4];
#pragma unroll
            for (int q = 0; q < 4; ++q) {
                acc[q][0] = accb[q][0]; acc[q][1] = accb[q][1];
                acc[q][2] = accb[q][0]; acc[q][3] = accb[q][1];
            }

#pragma unroll 4
            for (int kk = 0; kk < KK1; ++kk) {
                uint32_t a0 = abuf[kk & 3][0], a1 = abuf[kk & 3][1];
                uint32_t a2 = abuf[kk & 3][2], a3 = abuf[kk & 3][3];
                if (kk + 4 < KK1) {
                    if (kk == 28)                       // h1(p-2) ready (all);
                        wait_ge(&g_c1, 64u * p);        // overlapped by kk<28
                    ldkk(abuf[kk & 3], kk + 4, pH0, pH1, SPLIT1, aoff);
                }
                const uint32_t* bp = sWl + (kk * 8 + t4) * WSTR + g;
#pragma unroll
                for (int q = 0; q < 4; ++q)
                    mma16(acc[q], a0, a1, a2, a3, bp[q * 8], bp[4 * WSTR + q * 8]);
            }

            uint32_t* hw = g_h1w[(p - 1) & 3];
            float hv[4];
#pragma unroll
            for (int pr = 0; pr < 4; ++pr) {
                float cn2 = sigm(acc[1][pr]) * creg[pr]
                          + sigm(acc[0][pr]) * fast_tanh(acc[2][pr]);
                creg[pr] = cn2;
                hv[pr] = sigm(acc[3][pr]) * fast_tanh(cn2);
            }
            __stcg(&hw[kpIdx * BSZ + rowa],     packbf2(hv[0], hv[1]));
            __stcg(&hw[kpIdx * BSZ + rowa + 8], packbf2(hv[2], hv[3]));
            wg_post(&g_c1, tid7, barid);               // g_c1 -> 64*(p+1)
        }
    }

    // ---- exit protocol: reset counters for the next graph replay ----
    __syncthreads();
    if (tid == 0) redrel(&g_done);
    if (cta == 0 && tid == 0) {
        unsigned v;
        do {
            asm volatile("ld.acquire.gpu.global.u32 %0, [%1];" : "=r"(v) : "l"(&g_done));
        } while ((int)(v - NC) < 0);
        *(volatile unsigned*)&g_c0 = 0u;
        *(volatile unsigned*)&g_c1 = 0u;
        *(volatile unsigned*)&g_done = 0u;
    }
}

// x[b][t][i] -> pair-words [t][kp][b]
__global__ void xpose_kernel(const float* __restrict__ x) {
    int idx = blockIdx.x * blockDim.x + threadIdx.x;
    if (idx < SEQ * 32 * BSZ) {
        int b  = idx & 63;
        int kp = (idx >> 6) & 31;
        int t  = idx >> 11;
        const float* xe = x + ((b * SEQ) + t) * 64 + 2 * kp;
        g_xw[idx] = packbf2(xe[0], xe[1]);
    }
}

extern "C" void kernel_launch(void* const* d_in, const int* in_sizes, int n_in,
                              void* d_out, int out_size) {
    (void)in_sizes; (void)n_in; (void)out_size;
    const float* x   = (const float*)d_in[0];
    const float* W0  = (const float*)d_in[1];
    const float* b0  = (const float*)d_in[2];
    const float* W1  = (const float*)d_in[3];
    const float* b1  = (const float*)d_in[4];
    const float* Wfc = (const float*)d_in[5];
    const float* bfc = (const float*)d_in[6];
    float* out = (float*)d_out;

    cudaFuncSetAttribute(lstm_persist,
                         cudaFuncAttributeMaxDynamicSharedMemorySize, SMEM_BYTES);

    xpose_kernel<<<(SEQ * 32 * BSZ + 255) / 256, 256>>>(x);
    lstm_persist<<<NC, NTHR, SMEM_BYTES>>>(W0, b0, W1, b1, Wfc, bfc, out);
}

// round 13
// speedup vs baseline: 1.5872x; 1.5872x over previous
#include <cuda_runtime.h>
#include <cuda_bf16.h>
#include <cstdint>

// ---------------------------------------------------------------------------
// 2-layer LSTM, B=64, S=512, I=64, H=512, fc head on final h1.
// R13 topology: 64 persistent CTAs x 256 threads, ONE LAYER PER CTA:
//   CTAs 0-31  = layer0, each owns 16 gate-columns (K=576, 9 chunks)
//   CTAs 32-63 = layer1, each owns 16 gate-columns (K=1024, 16 chunks)
// 8 warps = two 4-warp N-teams (cols 0-7 / 8-15) sharing ONE cp.async A-ring
// -> A broadcast traffic halved, no intra-SM cross-layer contention.
// Sync: R7's aggregated release counters, 32 posts/phase/layer:
//   g_c0 = 64 (init, all CTAs) + 32*(q+1) after all layer0 finish phase q.
//   g_c1 = 32*(q+1) after all layer1 finish phase q (equalizer = "phase 0").
// h0 ring 8 deep (layer0 runs ahead), h1 ring 4 deep. c in registers.
// bf16 mma.m16n8k16 fp32-acc. Exit protocol resets counters (replay-safe).
// ---------------------------------------------------------------------------

#define NC    64
#define NTHR  256
#define BSZ   64
#define SEQ   512

#define AROWW 64                      // words per kp-row in gmem (b dim)
#define ASTR  72                      // padded words per kp-row in SMEM
#define CHKP  32                      // kp-rows per chunk
#define SLOTW (CHKP*ASTR)             // 2304 words per slot
#define NSLOT 4
#define WSTR  72                      // sW words per kp-row (64 cols + pad, 72%32==8)

#define KP0   288                     // layer0 K/2
#define KP1   512                     // layer1 K/2
#define NCH0  9
#define NCH1  16

#define SW_OFF    0
#define SBIAS_OFF (KP1*WSTR)                  // 36864 (layer0 uses less)
#define SA_OFF    (SBIAS_OFF + 64)
#define SMEM_WORDS (SA_OFF + NSLOT*SLOTW)     // 46144
#define SMEM_BYTES (SMEM_WORDS*4)             // 184576

// persistent state (device globals; allocation forbidden)
__device__ uint32_t g_xw[SEQ*32*BSZ];     // [t][kp<32][b] bf16x2
__device__ uint32_t g_h0w[8][256*BSZ];    // 8-deep ring [kp][b]
__device__ uint32_t g_h1w[4][256*BSZ];    // 4-deep ring
__device__ unsigned g_c0;                 // layer0 counter
__device__ unsigned g_c1;                 // layer1 counter
__device__ unsigned g_done;               // exit protocol

__device__ __forceinline__ uint32_t packbf2(float lo, float hi) {
    uint32_t r;
    asm("cvt.rn.bf16x2.f32 %0, %1, %2;" : "=r"(r) : "f"(hi), "f"(lo));
    return r;
}

__device__ __forceinline__ void mma16(float (&d)[4],
                                      uint32_t a0, uint32_t a1, uint32_t a2, uint32_t a3,
                                      uint32_t b0, uint32_t b1) {
    asm volatile(
        "mma.sync.aligned.m16n8k16.row.col.f32.bf16.bf16.f32 "
        "{%0,%1,%2,%3}, {%4,%5,%6,%7}, {%8,%9}, {%0,%1,%2,%3};"
        : "+f"(d[0]), "+f"(d[1]), "+f"(d[2]), "+f"(d[3])
        : "r"(a0), "r"(a1), "r"(a2), "r"(a3), "r"(b0), "r"(b1));
}

__device__ __forceinline__ float fast_tanh(float x) {
    float r;
    asm("tanh.approx.f32 %0, %1;" : "=f"(r) : "f"(x));
    return r;
}
__device__ __forceinline__ float sigm(float x) {
    return 0.5f * fast_tanh(0.5f * x) + 0.5f;
}

__device__ __forceinline__ void cpa16(uint32_t d, const uint32_t* s) {
    asm volatile("cp.async.cg.shared.global [%0], [%1], 16;" :: "r"(d), "l"(s) : "memory");
}
#define CP_COMMIT() asm volatile("cp.async.commit_group;" ::: "memory")
#define CP_WAIT3()  asm volatile("cp.async.wait_group 3;" ::: "memory")

__device__ __forceinline__ unsigned ldacq(const unsigned* p) {
    unsigned v;
    asm volatile("ld.acquire.gpu.global.u32 %0, [%1];" : "=r"(v) : "l"(p));
    return v;
}
__device__ __forceinline__ void redrel(unsigned* p) {
    asm volatile("red.release.gpu.global.add.u32 [%0], %1;" :: "l"(p), "r"(1u) : "memory");
}
// spin until *ctr >= tgt (single hot word, coalesced acquire loads)
__device__ __forceinline__ void wait_ge(unsigned* ctr, unsigned tgt) {
    while ((int)(ldacq(ctr) - tgt) < 0) { }
}

__global__ void __launch_bounds__(NTHR, 1)
lstm_persist(const float* __restrict__ W0, const float* __restrict__ b0,
             const float* __restrict__ W1, const float* __restrict__ b1,
             const float* __restrict__ Wfc, const float* __restrict__ bfc,
             float* __restrict__ out) {
    extern __shared__ uint32_t sm[];
    float* sBias = (float*)(sm + SBIAS_OFF);

    const int cta  = blockIdx.x;
    const int tid  = threadIdx.x;
    const int lyr  = (cta >= 32);               // 0 = layer0, 1 = layer1
    const int lc   = cta & 31;                  // layer-local CTA index
    const int n0   = lc * 16;                   // gate-column base (16 cols)
    const int lane = tid & 31, wrp = tid >> 5;
    const int wrp4 = wrp & 3;                   // M-warp within team
    const int team = wrp >> 2;                  // N-team: cols 0-7 / 8-15
    const int g    = lane >> 2, t4 = lane & 3;
    const int rowa = wrp4 * 16 + g;

    // A-ring staging duty: 256 threads, 32B each -> 8KB chunk
    const int ldr  = tid >> 3;                  // kp-row (0..31)
    const int ldc  = (tid & 7) * 8;             // word col base (8 words)
    const int thrOff = ldr * AROWW + ldc;

    const uint32_t smBase = (uint32_t)__cvta_generic_to_shared(sm);
    const uint32_t saThr  = smBase + (SA_OFF + ldr * ASTR + ldc) * 4;
    const uint32_t* sA    = sm + SA_OFF;
    const int teamW = team * 32;                // weight/bias word offset
    const int kpIdx = lc * 8 + team * 4 + t4;   // stored kp word index

    const int NCH = lyr ? NCH1 : NCH0;
    const int KW  = lyr ? KP1 : KP0;

    // ---- prologue: zero h slots read as h(-1) ----
    for (int e = cta * NTHR + tid; e < 256 * BSZ; e += NC * NTHR) {
        g_h0w[7][e] = 0u;
        g_h1w[3][e] = 0u;
    }

    // ---- prologue: this layer's 16-col weight slice -> SMEM bf16x2 ----
    {
        const float* W    = lyr ? W1 : W0;
        const float* bias = lyr ? b1 : b0;
        for (int e = tid; e < KW * 64; e += NTHR) {
            int kp = e >> 6, m = e & 63;        // m = team*32 + q*8 + j
            int q = (m >> 3) & 3, j = m & 7, tm = m >> 5;
            const float* w = W + (2 * kp) * 2048 + q * 512 + n0 + tm * 8 + j;
            sm[SW_OFF + kp * WSTR + m] = packbf2(w[0], w[2048]);
        }
        if (tid < 64) {
            int q = (tid >> 3) & 3, j = tid & 7, tm = tid >> 5;
            sBias[tid] = bias[q * 512 + n0 + tm * 8 + j];
        }
    }

    __syncthreads();
    if (tid == 0) redrel(&g_c0);        // init post by ALL 64 CTAs -> g_c0=64

    float creg[4] = {0.f, 0.f, 0.f, 0.f};
    float accb[4][2];
#pragma unroll
    for (int q = 0; q < 4; ++q) {
        accb[q][0] = sBias[teamW + q * 8 + 2 * t4];
        accb[q][1] = sBias[teamW + q * 8 + 2 * t4 + 1];
    }

    if (!lyr) {
        // =============== layer 0: phases p = 0..511, computes t=p ===========
        for (int p = 0; p < SEQ; ++p) {
            const uint32_t* pX = g_xw + p * (32 * BSZ) + thrOff;
            const uint32_t* pH = g_h0w[(p + 7) & 7] + thrOff;    // h0(p-1)

            // chunk 0 = x (no dependency) -> issue before the wait
            cpa16(saThr,      pX);
            cpa16(saThr + 16, pX + 4);
            CP_COMMIT();
            wait_ge(&g_c0, 64u + 32u * p);             // all h0(p-1) written
#pragma unroll
            for (int k = 1; k < 3; ++k) {              // chunks 1,2 = h0 rows
                const uint32_t* s = pH + (k - 1) * (CHKP * AROWW);
                uint32_t d = saThr + (k & 3) * (SLOTW * 4);
                cpa16(d, s); cpa16(d + 16, s + 4);
                CP_COMMIT();
            }

            float acc[4][4];
#pragma unroll
            for (int q = 0; q < 4; ++q) {
                acc[q][0] = accb[q][0]; acc[q][1] = accb[q][1];
                acc[q][2] = accb[q][0]; acc[q][3] = accb[q][1];
            }

            for (int c = 0; c < NCH0; ++c) {
                int cn = c + 3;
                if (cn < NCH0) {
                    const uint32_t* s = pH + (cn - 1) * (CHKP * AROWW);
                    uint32_t d = saThr + (cn & 3) * (SLOTW * 4);
                    cpa16(d, s); cpa16(d + 16, s + 4);
                }
                CP_COMMIT();
                CP_WAIT3();
                __syncthreads();
                const uint32_t* As = sA + (c & 3) * SLOTW;
#pragma unroll
                for (int k16 = 0; k16 < 4; ++k16) {
                    const uint32_t* ap = As + (k16 * 8 + t4) * ASTR;
                    uint32_t a0 = ap[rowa];
                    uint32_t a1 = ap[rowa + 8];
                    uint32_t a2 = ap[4 * ASTR + rowa];
                    uint32_t a3 = ap[4 * ASTR + rowa + 8];
                    const uint32_t* bp = sm + ((c * 4 + k16) * 8 + t4) * WSTR + teamW + g;
#pragma unroll
                    for (int q = 0; q < 4; ++q)
                        mma16(acc[q], a0, a1, a2, a3, bp[q * 8], bp[4 * WSTR + q * 8]);
                }
            }

            // ring back-pressure: layer1 finished phase p-7 (read h0(p-8))
            if (p >= 7) wait_ge(&g_c1, 32u * (p - 6));

            uint32_t* hw = g_h0w[p & 7];
            float hv[4];
#pragma unroll
            for (int pr = 0; pr < 4; ++pr) {
                float cn2 = sigm(acc[1][pr]) * creg[pr]
                          + sigm(acc[0][pr]) * fast_tanh(acc[2][pr]);
                creg[pr] = cn2;
                hv[pr] = sigm(acc[3][pr]) * fast_tanh(cn2);
            }
            __stcg(&hw[kpIdx * BSZ + rowa],     packbf2(hv[0], hv[1]));
            __stcg(&hw[kpIdx * BSZ + rowa + 8], packbf2(hv[2], hv[3]));
            __syncthreads();
            if (tid == 0) redrel(&g_c0);               // -> 64 + 32*(p+1)
        }
    } else {
        // =============== layer 1: phases p = 1..512, computes t=p-1 =========
        __syncthreads();
        if (tid == 0) redrel(&g_c1);                   // equalizer -> 32
        for (int p = 1; p <= SEQ; ++p) {
            const uint32_t* pH0 = g_h0w[(p + 7) & 7] + thrOff;   // h0(p-1)
            const uint32_t* pH1 = g_h1w[(p + 2) & 3] + thrOff;   // h1(p-2)

            wait_ge(&g_c0, 64u + 32u * p);             // all h0(p-1) written
#pragma unroll
            for (int k = 0; k < 3; ++k) {              // chunks 0-2 = h0
                const uint32_t* s = pH0 + k * (CHKP * AROWW);
                uint32_t d = saThr + (k & 3) * (SLOTW * 4);
                cpa16(d, s); cpa16(d + 16, s + 4);
                CP_COMMIT();
            }

            float acc[4][4];
#pragma unroll
            for (int q = 0; q < 4; ++q) {
                acc[q][0] = accb[q][0]; acc[q][1] = accb[q][1];
                acc[q][2] = accb[q][0]; acc[q][3] = accb[q][1];
            }

            for (int c = 0; c < NCH1; ++c) {
                int cn = c + 3;
                if (cn < NCH1) {
                    if (cn == 8)                       // h1(p-2) all written;
                        wait_ge(&g_c1, 32u * p);       // overlapped w/ chunks 0-4
                    const uint32_t* s = (cn < 8)
                        ? pH0 + cn * (CHKP * AROWW)
                        : pH1 + (cn - 8) * (CHKP * AROWW);
                    uint32_t d = saThr + (cn & 3) * (SLOTW * 4);
                    cpa16(d, s); cpa16(d + 16, s + 4);
                }
                CP_COMMIT();
                CP_WAIT3();
                __syncthreads();
                const uint32_t* As = sA + (c & 3) * SLOTW;
#pragma unroll
                for (int k16 = 0; k16 < 4; ++k16) {
                    const uint32_t* ap = As + (k16 * 8 + t4) * ASTR;
                    uint32_t a0 = ap[rowa];
                    uint32_t a1 = ap[rowa + 8];
                    uint32_t a2 = ap[4 * ASTR + rowa];
                    uint32_t a3 = ap[4 * ASTR + rowa + 8];
                    const uint32_t* bp = sm + ((c * 4 + k16) * 8 + t4) * WSTR + teamW + g;
#pragma unroll
                    for (int q = 0; q < 4; ++q)
                        mma16(acc[q], a0, a1, a2, a3, bp[q * 8], bp[4 * WSTR + q * 8]);
                }
            }

            uint32_t* hw = g_h1w[(p - 1) & 3];
            float hv[4];
#pragma unroll
            for (int pr = 0; pr < 4; ++pr) {
                float cn2 = sigm(acc[1][pr]) * creg[pr]
                          + sigm(acc[0][pr]) * fast_tanh(acc[2][pr]);
                creg[pr] = cn2;
                hv[pr] = sigm(acc[3][pr]) * fast_tanh(cn2);
            }
            __stcg(&hw[kpIdx * BSZ + rowa],     packbf2(hv[0], hv[1]));
            __stcg(&hw[kpIdx * BSZ + rowa + 8], packbf2(hv[2], hv[3]));
            __syncthreads();
            if (tid == 0) redrel(&g_c1);               // -> 32*(p+1)
        }

        // epilogue: cta 63 computes fc after ALL layer1 finish phase 512
        if (cta == 63) {
            wait_ge(&g_c1, 32u * (SEQ + 1));
            if (tid < BSZ) {
                const uint32_t* h = g_h1w[(SEQ - 1) & 3];
                float s0 = 0.f, s1 = 0.f;
#pragma unroll 4
                for (int kp = 0; kp < 256; ++kp) {
                    uint32_t w = __ldcg(&h[kp * BSZ + tid]);
                    float lo = __bfloat162float(__ushort_as_bfloat16((unsigned short)(w & 0xFFFF)));
                    float hi = __bfloat162float(__ushort_as_bfloat16((unsigned short)(w >> 16)));
                    s0 += lo * Wfc[2 * kp];
                    s1 += hi * Wfc[2 * kp + 1];
                }
                out[tid] = s0 + s1 + bfc[0];
            }
        }
    }

    // ---- exit protocol: reset counters for the next graph replay ----
    __syncthreads();
    if (tid == 0) redrel(&g_done);
    if (cta == 0 && tid == 0) {
        unsigned v;
        do {
            asm volatile("ld.acquire.gpu.global.u32 %0, [%1];" : "=r"(v) : "l"(&g_done));
        } while ((int)(v - NC) < 0);
        *(volatile unsigned*)&g_c0 = 0u;
        *(volatile unsigned*)&g_c1 = 0u;
        *(volatile unsigned*)&g_done = 0u;
    }
}

// x[b][t][i] -> pair-words [t][kp][b]
__global__ void xpose_kernel(const float* __restrict__ x) {
    int idx = blockIdx.x * blockDim.x + threadIdx.x;
    if (idx < SEQ * 32 * BSZ) {
        int b  = idx & 63;
        int kp = (idx >> 6) & 31;
        int t  = idx >> 11;
        const float* xe = x + ((b * SEQ) + t) * 64 + 2 * kp;
        g_xw[idx] = packbf2(xe[0], xe[1]);
    }
}

extern "C" void kernel_launch(void* const* d_in, const int* in_sizes, int n_in,
                              void* d_out, int out_size) {
    (void)in_sizes; (void)n_in; (void)out_size;
    const float* x   = (const float*)d_in[0];
    const float* W0  = (const float*)d_in[1];
    const float* b0  = (const float*)d_in[2];
    const float* W1  = (const float*)d_in[3];
    const float* b1  = (const float*)d_in[4];
    const float* Wfc = (const float*)d_in[5];
    const float* bfc = (const float*)d_in[6];
    float* out = (float*)d_out;

    cudaFuncSetAttribute(lstm_persist,
                         cudaFuncAttributeMaxDynamicSharedMemorySize, SMEM_BYTES);

    xpose_kernel<<<(SEQ * 32 * BSZ + 255) / 256, 256>>>(x);
    lstm_persist<<<NC, NTHR, SMEM_BYTES>>>(W0, b0, W1, b1, Wfc, bfc, out);
}

// round 14
// speedup vs baseline: 1.6747x; 1.0551x over previous
#include <cuda_runtime.h>
#include <cuda_bf16.h>
#include <cstdint>

// ---------------------------------------------------------------------------
// 2-layer LSTM, B=64, S=512, I=64, H=512, fc head on final h1.
// R14: 128 persistent CTAs x 256 threads, ONE LAYER PER CTA, 8 h-cols each:
//   CTAs 0-63  = layer0 (K=576 = x(64) + h0(512), 9 chunks)
//   CTAs 64-127= layer1 (K=1024 = h0(512) + h1(512), 16 chunks)
// 8 warps = 4 M-warps x 2 K-TEAMS (split-K): layer1 team0 = h0 half
// (chunks 0-7), team1 = h1 half (chunks 8-15); layer0 split 5/4 (x chunk
// prefetched before the wait). SMEM reduction + cell by team0.
// -> HMMA per SMSP per phase halves vs R13 (the measured tensor-issue floor).
// Sync: aggregated release counters (R7 primitive):
//   g_c0 = 128 (init, all CTAs) + 64*(q+1) after all layer0 finish phase q.
//   g_c1 = 64*(q+1) after all layer1 finish phase q (q=0 equalizer).
// h0 ring 8 deep, h1 ring 4 deep, c in registers (team0).
// bf16 mma.m16n8k16 fp32-acc. Exit protocol resets counters (replay-safe).
// ---------------------------------------------------------------------------

#define NC    128
#define NTHR  256
#define BSZ   64
#define SEQ   512

#define AROWW 64                      // words per kp-row in gmem (b dim)
#define ASTR  72                      // padded words per kp-row in SMEM
#define CHKP  32                      // kp-rows per chunk
#define SLOTW (CHKP*ASTR)             // 2304 words per slot
#define NSLOT 4
#define WSTR  40                      // sW padded words per kp-row

#define KP0   288                     // layer0 K/2 rows
#define KP1   512                     // layer1 K/2 rows

#define SW_OFF    0
#define SBIAS_OFF 20480                       // 512*40 max weight words
#define SRED_OFF  (SBIAS_OFF + 32)            // 2048-word reduction buffer
#define SA_OFF    (SRED_OFF + 2048)           // 22560 (16B aligned)
#define SMEM_WORDS (SA_OFF + 2*NSLOT*SLOTW)   // 40992
#define SMEM_BYTES (SMEM_WORDS*4)             // 163968

// persistent state (device globals; allocation forbidden)
__device__ uint32_t g_xw[SEQ*32*BSZ];     // [t][kp<32][b] bf16x2
__device__ uint32_t g_h0w[8][256*BSZ];    // 8-deep ring [kp][b]
__device__ uint32_t g_h1w[4][256*BSZ];    // 4-deep ring
__device__ unsigned g_c0;                 // layer0 counter
__device__ unsigned g_c1;                 // layer1 counter
__device__ unsigned g_done;               // exit protocol

__device__ __forceinline__ uint32_t packbf2(float lo, float hi) {
    uint32_t r;
    asm("cvt.rn.bf16x2.f32 %0, %1, %2;" : "=r"(r) : "f"(hi), "f"(lo));
    return r;
}

__device__ __forceinline__ void mma16(float (&d)[4],
                                      uint32_t a0, uint32_t a1, uint32_t a2, uint32_t a3,
                                      uint32_t b0, uint32_t b1) {
    asm volatile(
        "mma.sync.aligned.m16n8k16.row.col.f32.bf16.bf16.f32 "
        "{%0,%1,%2,%3}, {%4,%5,%6,%7}, {%8,%9}, {%0,%1,%2,%3};"
        : "+f"(d[0]), "+f"(d[1]), "+f"(d[2]), "+f"(d[3])
        : "r"(a0), "r"(a1), "r"(a2), "r"(a3), "r"(b0), "r"(b1));
}

__device__ __forceinline__ float fast_tanh(float x) {
    float r;
    asm("tanh.approx.f32 %0, %1;" : "=f"(r) : "f"(x));
    return r;
}
__device__ __forceinline__ float sigm(float x) {
    return 0.5f * fast_tanh(0.5f * x) + 0.5f;
}

__device__ __forceinline__ void cpa16(uint32_t d, const uint32_t* s) {
    asm volatile("cp.async.cg.shared.global [%0], [%1], 16;" :: "r"(d), "l"(s) : "memory");
}
#define CP_COMMIT() asm volatile("cp.async.commit_group;" ::: "memory")
#define CP_WAIT3()  asm volatile("cp.async.wait_group 3;" ::: "memory")
#define BAR_WG(id)  asm volatile("bar.sync %0, 128;" :: "r"(id) : "memory")

__device__ __forceinline__ unsigned ldacq(const unsigned* p) {
    unsigned v;
    asm volatile("ld.acquire.gpu.global.u32 %0, [%1];" : "=r"(v) : "l"(p));
    return v;
}
__device__ __forceinline__ void redrel(unsigned* p) {
    asm volatile("red.release.gpu.global.add.u32 [%0], %1;" :: "l"(p), "r"(1u) : "memory");
}
__device__ __forceinline__ void wait_ge(unsigned* ctr, unsigned tgt) {
    while ((int)(ldacq(ctr) - tgt) < 0) { }
}

__device__ __forceinline__ void issue_chunk(const uint32_t* __restrict__ src,
                                            uint32_t dstAdr) {
    cpa16(dstAdr,      src);
    cpa16(dstAdr + 16, src + 4);
    cpa16(dstAdr + 32, src + 8);
    cpa16(dstAdr + 48, src + 12);
}

// chunk cn -> source pointer (pointers pre-offset by this thread's share)
__device__ __forceinline__ const uint32_t* chunk_src(int cn, int lyr,
        const uint32_t* pX, const uint32_t* pHa, const uint32_t* pHb) {
    if (!lyr) return (cn == 0) ? pX : pHa + (cn - 1) * (CHKP * AROWW);
    return (cn < 8) ? pHa + cn * (CHKP * AROWW)
                    : pHb + (cn - 8) * (CHKP * AROWW);
}

__global__ void __launch_bounds__(NTHR, 1)
lstm_persist(const float* __restrict__ W0, const float* __restrict__ b0,
             const float* __restrict__ W1, const float* __restrict__ b1,
             const float* __restrict__ Wfc, const float* __restrict__ bfc,
             float* __restrict__ out) {
    extern __shared__ uint32_t sm[];
    float* sBias = (float*)(sm + SBIAS_OFF);
    float* sRed  = (float*)(sm + SRED_OFF);

    const int cta  = blockIdx.x;
    const int tid  = threadIdx.x;
    const int lyr  = cta >> 6;                 // 0 = layer0, 1 = layer1
    const int lc   = cta & 63;                 // layer-local CTA index
    const int n0   = lc * 8;                   // h-column base (8 cols)
    const int lane = tid & 31, wrp = tid >> 5;
    const int wrp4 = wrp & 3;                  // M-warp within team
    const int team = wrp >> 2;                 // K-team (0 = low half)
    const int g    = lane >> 2, t4 = lane & 3;
    const int rowa = wrp4 * 16 + g;

    const int tid7 = tid & 127;                // team-local tid
    const int ldr  = tid7 >> 2;
    const int ldc  = (tid7 & 3) * 16;
    const int thrOff = ldr * AROWW + ldc;

    const int barid = 1 + team;
    const uint32_t smBase = (uint32_t)__cvta_generic_to_shared(sm);
    const uint32_t saTeam = smBase + (SA_OFF + team * NSLOT * SLOTW) * 4
                          + (ldr * ASTR + ldc) * 4;
    const uint32_t* sAteam = sm + SA_OFF + team * NSLOT * SLOTW;
    const int kpIdx = lc * 4 + t4;

    // team chunk ranges
    const int base = lyr ? (team ? 8 : 0) : (team ? 5 : 0);
    const int nCh  = lyr ? 8 : (team ? 4 : 5);

    // ---- prologue: zero h slots read as h(-1) ----
    for (int e = cta * NTHR + tid; e < 256 * BSZ; e += NC * NTHR) {
        g_h0w[7][e] = 0u;
        g_h1w[3][e] = 0u;
    }

    // ---- prologue: full-K weights for this CTA's 8 cols -> SMEM bf16x2 ----
    {
        const float* W    = lyr ? W1 : W0;
        const float* bias = lyr ? b1 : b0;
        const int KW = lyr ? KP1 : KP0;
        for (int e = tid; e < KW * 32; e += NTHR) {
            int kp = e >> 5, c = e & 31;
            int q = c >> 3, j = c & 7;
            const float* w = W + (2 * kp) * 2048 + q * 512 + n0 + j;
            sm[SW_OFF + kp * WSTR + c] = packbf2(w[0], w[2048]);
        }
        if (tid < 32) {
            int q = tid >> 3, j = tid & 7;
            sBias[tid] = bias[q * 512 + n0 + j];
        }
    }

    __syncthreads();
    if (tid == 0) {
        redrel(&g_c0);                          // init: g_c0 -> 128
        if (lyr) redrel(&g_c1);                 // equalizer: g_c1 -> 64
    }

    float creg[4] = {0.f, 0.f, 0.f, 0.f};
    float accb[4][2];
#pragma unroll
    for (int q = 0; q < 4; ++q) {
        accb[q][0] = team ? 0.f : sBias[q * 8 + 2 * t4];
        accb[q][1] = team ? 0.f : sBias[q * 8 + 2 * t4 + 1];
    }

    const int pStart = lyr ? 1 : 0;
    const int pEnd   = lyr ? SEQ : (SEQ - 1);

    for (int p = pStart; p <= pEnd; ++p) {
        const uint32_t* pX  = g_xw + p * (32 * BSZ) + thrOff;
        const uint32_t* pHa = g_h0w[(p + 7) & 7] + thrOff;      // h0(p-1)
        const uint32_t* pHb = g_h1w[(p + 2) & 3] + thrOff;      // h1(p-2)

        // ---- dependency waits + ring prologue (per team) ----
        if (!lyr && !team) {
            issue_chunk(pX, saTeam);                    // x: no dependency
            CP_COMMIT();
            wait_ge(&g_c0, 128u + 64u * p);             // h0(p-1) all written
            issue_chunk(chunk_src(1, 0, pX, pHa, pHb), saTeam + 1 * (SLOTW * 4));
            CP_COMMIT();
            issue_chunk(chunk_src(2, 0, pX, pHa, pHb), saTeam + 2 * (SLOTW * 4));
            CP_COMMIT();
        } else {
            if (lyr && team) wait_ge(&g_c1, 64u * p);   // h1(p-2) all written
            else             wait_ge(&g_c0, 128u + 64u * p);  // h0(p-1)
#pragma unroll
            for (int k = 0; k < 3; ++k) {
                issue_chunk(chunk_src(base + k, lyr, pX, pHa, pHb),
                            saTeam + (k & 3) * (SLOTW * 4));
                CP_COMMIT();
            }
        }

        float acc[4][4];
#pragma unroll
        for (int q = 0; q < 4; ++q) {
            acc[q][0] = accb[q][0]; acc[q][1] = accb[q][1];
            acc[q][2] = accb[q][0]; acc[q][3] = accb[q][1];
        }

        // ---- chunk pipeline: group index == local chunk index ----
        for (int c = 0; c < nCh; ++c) {
            int cl = c + 3;
            if (cl < nCh)
                issue_chunk(chunk_src(base + cl, lyr, pX, pHa, pHb),
                            saTeam + (cl & 3) * (SLOTW * 4));
            CP_COMMIT();
            CP_WAIT3();
            BAR_WG(barid);
            const uint32_t* As = sAteam + (c & 3) * SLOTW;
            const int cn = base + c;
#pragma unroll
            for (int k16 = 0; k16 < 4; ++k16) {
                const uint32_t* ap = As + (k16 * 8 + t4) * ASTR;
                uint32_t a0 = ap[rowa];
                uint32_t a1 = ap[rowa + 8];
                uint32_t a2 = ap[4 * ASTR + rowa];
                uint32_t a3 = ap[4 * ASTR + rowa + 8];
                const uint32_t* bp = sm + ((cn * 4 + k16) * 8 + t4) * WSTR + g;
#pragma unroll
                for (int q = 0; q < 4; ++q)
                    mma16(acc[q], a0, a1, a2, a3, bp[q * 8], bp[4 * WSTR + q * 8]);
            }
        }

        // ---- split-K reduction: team1 -> SMEM, team0 adds + cell + store ----
        if (team) {
            float* red = sRed + (wrp4 * 32 + lane) * 16;
#pragma unroll
            for (int q = 0; q < 4; ++q)
                *(float4*)(red + q * 4) = *(float4*)acc[q];
        }
        __syncthreads();
        if (!team) {
            const float* red = sRed + (wrp4 * 32 + lane) * 16;
#pragma unroll
            for (int q = 0; q < 4; ++q) {
                float4 r4 = *(const float4*)(red + q * 4);
                acc[q][0] += r4.x; acc[q][1] += r4.y;
                acc[q][2] += r4.z; acc[q][3] += r4.w;
            }
            // h0-ring back-pressure before overwriting slot p&7 (layer0 only)
            if (!lyr && p >= 7) wait_ge(&g_c1, 64u * (p - 6));

            uint32_t* hw = lyr ? g_h1w[(p - 1) & 3] : g_h0w[p & 7];
            float hv[4];
#pragma unroll
            for (int pr = 0; pr < 4; ++pr) {
                float cn2 = sigm(acc[1][pr]) * creg[pr]
                          + sigm(acc[0][pr]) * fast_tanh(acc[2][pr]);
                creg[pr] = cn2;
                hv[pr] = sigm(acc[3][pr]) * fast_tanh(cn2);
            }
            __stcg(&hw[kpIdx * BSZ + rowa],     packbf2(hv[0], hv[1]));
            __stcg(&hw[kpIdx * BSZ + rowa + 8], packbf2(hv[2], hv[3]));
        }
        __syncthreads();
        if (tid == 0) redrel(lyr ? &g_c1 : &g_c0);
    }

    // ---- epilogue: fc head on final h1 (one layer1 CTA) ----
    if (cta == NC - 1) {
        wait_ge(&g_c1, 64u * (SEQ + 1));
        if (tid < BSZ) {
            const uint32_t* h = g_h1w[(SEQ - 1) & 3];
            float s0 = 0.f, s1 = 0.f;
#pragma unroll 4
            for (int kp = 0; kp < 256; ++kp) {
                uint32_t w = __ldcg(&h[kp * BSZ + tid]);
                float lo = __bfloat162float(__ushort_as_bfloat16((unsigned short)(w & 0xFFFF)));
                float hi = __bfloat162float(__ushort_as_bfloat16((unsigned short)(w >> 16)));
                s0 += lo * Wfc[2 * kp];
                s1 += hi * Wfc[2 * kp + 1];
            }
            out[tid] = s0 + s1 + bfc[0];
        }
    }

    // ---- exit protocol: reset counters for the next graph replay ----
    __syncthreads();
    if (tid == 0) redrel(&g_done);
    if (cta == 0 && tid == 0) {
        unsigned v;
        do {
            asm volatile("ld.acquire.gpu.global.u32 %0, [%1];" : "=r"(v) : "l"(&g_done));
        } while ((int)(v - NC) < 0);
        *(volatile unsigned*)&g_c0 = 0u;
        *(volatile unsigned*)&g_c1 = 0u;
        *(volatile unsigned*)&g_done = 0u;
    }
}

// x[b][t][i] -> pair-words [t][kp][b]
__global__ void xpose_kernel(const float* __restrict__ x) {
    int idx = blockIdx.x * blockDim.x + threadIdx.x;
    if (idx < SEQ * 32 * BSZ) {
        int b  = idx & 63;
        int kp = (idx >> 6) & 31;
        int t  = idx >> 11;
        const float* xe = x + ((b * SEQ) + t) * 64 + 2 * kp;
        g_xw[idx] = packbf2(xe[0], xe[1]);
    }
}

extern "C" void kernel_launch(void* const* d_in, const int* in_sizes, int n_in,
                              void* d_out, int out_size) {
    (void)in_sizes; (void)n_in; (void)out_size;
    const float* x   = (const float*)d_in[0];
    const float* W0  = (const float*)d_in[1];
    const float* b0  = (const float*)d_in[2];
    const float* W1  = (const float*)d_in[3];
    const float* b1  = (const float*)d_in[4];
    const float* Wfc = (const float*)d_in[5];
    const float* bfc = (const float*)d_in[6];
    float* out = (float*)d_out;

    cudaFuncSetAttribute(lstm_persist,
                         cudaFuncAttributeMaxDynamicSharedMemorySize, SMEM_BYTES);

    xpose_kernel<<<(SEQ * 32 * BSZ + 255) / 256, 256>>>(x);
    lstm_persist<<<NC, NTHR, SMEM_BYTES>>>(W0, b0, W1, b1, Wfc, bfc, out);
}

// round 16
// speedup vs baseline: 1.8316x; 1.0937x over previous
#include <cuda_runtime.h>
#include <cuda_bf16.h>
#include <cstdint>

// ---------------------------------------------------------------------------
// 2-layer LSTM, B=64, S=512, I=64, H=512, fc head on final h1.
// R16 = R14 topology (128 CTAs x 256 thr, one layer per CTA, 8 h-cols,
// split-K across two 4-warp teams) with a safely re-engineered cycle:
//  * single-poller waits: warp0 of a team polls the counter, team bar
//    releases -> poll storm removed (isolated test of that theory).
//  * OWNER INVERSION, one __syncthreads per phase: team0 (non-critical,
//    data ready early) dumps partial acc into parity-double-buffered sRed
//    BEFORE the sync; team1 (g_c1 wait on h1(p-2) = the recurrence edge)
//    reduces + cell + stores + posts right after its GEMM. sRed overwrite
//    at p+2 is behind sync(p+1), which team1 enters only after consuming
//    phase p -> safe with a single sync. (R15's split arrive/wait bars
//    deadlocked via arrival stacking; not used.)
// Counters: g_c0 = 128 + 64*(q+1) after all layer0 finish phase q;
//           g_c1 = 64*(q+1) after all layer1 finish phase q (q=0 equalizer).
// h0 ring 8 deep, h1 ring 4 deep, creg/bias owned by team1.
// bf16 mma.m16n8k16 fp32-acc. Exit protocol resets counters (replay-safe).
// ---------------------------------------------------------------------------

#define NC    128
#define NTHR  256
#define BSZ   64
#define SEQ   512

#define AROWW 64
#define ASTR  72
#define CHKP  32
#define SLOTW (CHKP*ASTR)
#define NSLOT 4
#define WSTR  40

#define KP0   288
#define KP1   512

#define SW_OFF    0
#define SBIAS_OFF 20480                       // 512*40 max weight words
#define SRED_OFF  (SBIAS_OFF + 32)            // 2 x 2048-word acc buffers
#define SA_OFF    (SRED_OFF + 4096)           // 24608
#define SMEM_WORDS (SA_OFF + 2*NSLOT*SLOTW)   // 43040
#define SMEM_BYTES (SMEM_WORDS*4)             // 172160

__device__ uint32_t g_xw[SEQ*32*BSZ];
__device__ uint32_t g_h0w[8][256*BSZ];
__device__ uint32_t g_h1w[4][256*BSZ];
__device__ unsigned g_c0;
__device__ unsigned g_c1;
__device__ unsigned g_done;

__device__ __forceinline__ uint32_t packbf2(float lo, float hi) {
    uint32_t r;
    asm("cvt.rn.bf16x2.f32 %0, %1, %2;" : "=r"(r) : "f"(hi), "f"(lo));
    return r;
}

__device__ __forceinline__ void mma16(float (&d)[4],
                                      uint32_t a0, uint32_t a1, uint32_t a2, uint32_t a3,
                                      uint32_t b0, uint32_t b1) {
    asm volatile(
        "mma.sync.aligned.m16n8k16.row.col.f32.bf16.bf16.f32 "
        "{%0,%1,%2,%3}, {%4,%5,%6,%7}, {%8,%9}, {%0,%1,%2,%3};"
        : "+f"(d[0]), "+f"(d[1]), "+f"(d[2]), "+f"(d[3])
        : "r"(a0), "r"(a1), "r"(a2), "r"(a3), "r"(b0), "r"(b1));
}

__device__ __forceinline__ float fast_tanh(float x) {
    float r;
    asm("tanh.approx.f32 %0, %1;" : "=f"(r) : "f"(x));
    return r;
}
__device__ __forceinline__ float sigm(float x) {
    return 0.5f * fast_tanh(0.5f * x) + 0.5f;
}

__device__ __forceinline__ void cpa16(uint32_t d, const uint32_t* s) {
    asm volatile("cp.async.cg.shared.global [%0], [%1], 16;" :: "r"(d), "l"(s) : "memory");
}
#define CP_COMMIT() asm volatile("cp.async.commit_group;" ::: "memory")
#define CP_WAIT3()  asm volatile("cp.async.wait_group 3;" ::: "memory")
#define BAR_WG(id)  asm volatile("bar.sync %0, 128;" :: "r"(id) : "memory")

__device__ __forceinline__ unsigned ldacq(const unsigned* p) {
    unsigned v;
    asm volatile("ld.acquire.gpu.global.u32 %0, [%1];" : "=r"(v) : "l"(p));
    return v;
}
__device__ __forceinline__ void redrel(unsigned* p) {
    asm volatile("red.release.gpu.global.add.u32 [%0], %1;" :: "l"(p), "r"(1u) : "memory");
}
__device__ __forceinline__ void wait_ge(unsigned* ctr, unsigned tgt) {
    while ((int)(ldacq(ctr) - tgt) < 0) { }
}
// single-poller team wait: warp0 of the team polls, named bar releases team
__device__ __forceinline__ void team_wait(unsigned* ctr, unsigned tgt,
                                          int wrp4, int barid) {
    if (wrp4 == 0) wait_ge(ctr, tgt);
    BAR_WG(barid);
}

__device__ __forceinline__ void issue_chunk(const uint32_t* __restrict__ src,
                                            uint32_t dstAdr) {
    cpa16(dstAdr,      src);
    cpa16(dstAdr + 16, src + 4);
    cpa16(dstAdr + 32, src + 8);
    cpa16(dstAdr + 48, src + 12);
}

__device__ __forceinline__ const uint32_t* chunk_src(int cn, int lyr,
        const uint32_t* pX, const uint32_t* pHa, const uint32_t* pHb) {
    if (!lyr) return (cn == 0) ? pX : pHa + (cn - 1) * (CHKP * AROWW);
    return (cn < 8) ? pHa + cn * (CHKP * AROWW)
                    : pHb + (cn - 8) * (CHKP * AROWW);
}

__global__ void __launch_bounds__(NTHR, 1)
lstm_persist(const float* __restrict__ W0, const float* __restrict__ b0,
             const float* __restrict__ W1, const float* __restrict__ b1,
             const float* __restrict__ Wfc, const float* __restrict__ bfc,
             float* __restrict__ out) {
    extern __shared__ uint32_t sm[];
    float* sBias = (float*)(sm + SBIAS_OFF);

    const int cta  = blockIdx.x;
    const int tid  = threadIdx.x;
    const int lyr  = cta >> 6;
    const int lc   = cta & 63;
    const int n0   = lc * 8;
    const int lane = tid & 31, wrp = tid >> 5;
    const int wrp4 = wrp & 3;
    const int team = wrp >> 2;
    const int g    = lane >> 2, t4 = lane & 3;
    const int rowa = wrp4 * 16 + g;

    const int tid7 = tid & 127;
    const int ldr  = tid7 >> 2;
    const int ldc  = (tid7 & 3) * 16;
    const int thrOff = ldr * AROWW + ldc;

    const int barid = 1 + team;
    const uint32_t smBase = (uint32_t)__cvta_generic_to_shared(sm);
    const uint32_t saTeam = smBase + (SA_OFF + team * NSLOT * SLOTW) * 4
                          + (ldr * ASTR + ldc) * 4;
    const uint32_t* sAteam = sm + SA_OFF + team * NSLOT * SLOTW;
    const int kpIdx = lc * 4 + t4;

    const int base = lyr ? (team ? 8 : 0) : (team ? 5 : 0);
    const int nCh  = lyr ? 8 : (team ? 4 : 5);

    // ---- prologue ----
    for (int e = cta * NTHR + tid; e < 256 * BSZ; e += NC * NTHR) {
        g_h0w[7][e] = 0u;
        g_h1w[3][e] = 0u;
    }
    {
        const float* W    = lyr ? W1 : W0;
        const float* bias = lyr ? b1 : b0;
        const int KW = lyr ? KP1 : KP0;
        for (int e = tid; e < KW * 32; e += NTHR) {
            int kp = e >> 5, c = e & 31;
            int q = c >> 3, j = c & 7;
            const float* w = W + (2 * kp) * 2048 + q * 512 + n0 + j;
            sm[SW_OFF + kp * WSTR + c] = packbf2(w[0], w[2048]);
        }
        if (tid < 32) {
            int q = tid >> 3, j = tid & 7;
            sBias[tid] = bias[q * 512 + n0 + j];
        }
    }

    __syncthreads();
    if (tid == 0) {
        redrel(&g_c0);                          // init: g_c0 -> 128
        if (lyr) redrel(&g_c1);                 // equalizer: g_c1 -> 64
    }

    float creg[4] = {0.f, 0.f, 0.f, 0.f};       // live in team1 only
    float accb[4][2];
#pragma unroll
    for (int q = 0; q < 4; ++q) {                // bias owned by team1
        accb[q][0] = team ? sBias[q * 8 + 2 * t4]     : 0.f;
        accb[q][1] = team ? sBias[q * 8 + 2 * t4 + 1] : 0.f;
    }

    const int pStart = lyr ? 1 : 0;
    const int pEnd   = lyr ? SEQ : (SEQ - 1);

    for (int p = pStart; p <= pEnd; ++p) {
        const uint32_t* pX  = g_xw + p * (32 * BSZ) + thrOff;
        const uint32_t* pHa = g_h0w[(p + 7) & 7] + thrOff;      // h0(p-1)
        const uint32_t* pHb = g_h1w[(p + 2) & 3] + thrOff;      // h1(p-2)

        // ---- dependency wait + ring prologue (per team) ----
        if (!lyr && !team) {
            issue_chunk(pX, saTeam);                    // x: no dependency
            CP_COMMIT();
            team_wait(&g_c0, 128u + 64u * p, wrp4, barid);
            issue_chunk(chunk_src(1, 0, pX, pHa, pHb), saTeam + 1 * (SLOTW * 4));
            CP_COMMIT();
            issue_chunk(chunk_src(2, 0, pX, pHa, pHb), saTeam + 2 * (SLOTW * 4));
            CP_COMMIT();
        } else {
            if (lyr && team) team_wait(&g_c1, 64u * p, wrp4, barid);
            else             team_wait(&g_c0, 128u + 64u * p, wrp4, barid);
#pragma unroll
            for (int k = 0; k < 3; ++k) {
                issue_chunk(chunk_src(base + k, lyr, pX, pHa, pHb),
                            saTeam + (k & 3) * (SLOTW * 4));
                CP_COMMIT();
            }
        }

        float acc[4][4];
#pragma unroll
        for (int q = 0; q < 4; ++q) {
            acc[q][0] = accb[q][0]; acc[q][1] = accb[q][1];
            acc[q][2] = accb[q][0]; acc[q][3] = accb[q][1];
        }

        // ---- chunk pipeline: group index == local chunk index ----
        for (int c = 0; c < nCh; ++c) {
            int cl = c + 3;
            if (cl < nCh)
                issue_chunk(chunk_src(base + cl, lyr, pX, pHa, pHb),
                            saTeam + (cl & 3) * (SLOTW * 4));
            CP_COMMIT();
            CP_WAIT3();
            BAR_WG(barid);
            const uint32_t* As = sAteam + (c & 3) * SLOTW;
            const int cn = base + c;
#pragma unroll
            for (int k16 = 0; k16 < 4; ++k16) {
                const uint32_t* ap = As + (k16 * 8 + t4) * ASTR;
                uint32_t a0 = ap[rowa];
                uint32_t a1 = ap[rowa + 8];
                uint32_t a2 = ap[4 * ASTR + rowa];
                uint32_t a3 = ap[4 * ASTR + rowa + 8];
                const uint32_t* bp = sm + ((cn * 4 + k16) * 8 + t4) * WSTR + g;
#pragma unroll
                for (int q = 0; q < 4; ++q)
                    mma16(acc[q], a0, a1, a2, a3, bp[q * 8], bp[4 * WSTR + q * 8]);
            }
        }

        // ---- handoff: team0 dumps BEFORE the single sync; team1 tails ----
        float* red = (float*)(sm + SRED_OFF) + (p & 1) * 2048
                   + (wrp4 * 32 + lane) * 16;
        if (!team) {
#pragma unroll
            for (int q = 0; q < 4; ++q)
                *(float4*)(red + q * 4) = *(float4*)acc[q];
        }
        __syncthreads();                         // the ONE join per phase
        if (team) {
#pragma unroll
            for (int q = 0; q < 4; ++q) {
                float4 r4 = *(const float4*)(red + q * 4);
                acc[q][0] += r4.x; acc[q][1] += r4.y;
                acc[q][2] += r4.z; acc[q][3] += r4.w;
            }

            // h0-ring back-pressure before overwriting slot p&7 (layer0)
            if (!lyr && p >= 7) {
                if (wrp4 == 0) wait_ge(&g_c1, 64u * (p - 6));
                BAR_WG(barid);
            }

            uint32_t* hw = lyr ? g_h1w[(p - 1) & 3] : g_h0w[p & 7];
            float hv[4];
#pragma unroll
            for (int pr = 0; pr < 4; ++pr) {
                float cn2 = sigm(acc[1][pr]) * creg[pr]
                          + sigm(acc[0][pr]) * fast_tanh(acc[2][pr]);
                creg[pr] = cn2;
                hv[pr] = sigm(acc[3][pr]) * fast_tanh(cn2);
            }
            __stcg(&hw[kpIdx * BSZ + rowa],     packbf2(hv[0], hv[1]));
            __stcg(&hw[kpIdx * BSZ + rowa + 8], packbf2(hv[2], hv[3]));
            BAR_WG(barid);                       // order team1 stores
            if (tid7 == 0) redrel(lyr ? &g_c1 : &g_c0);
        }
    }

    // ---- epilogue: fc head on final h1 (one layer1 CTA) ----
    if (cta == NC - 1) {
        wait_ge(&g_c1, 64u * (SEQ + 1));
        if (tid < BSZ) {
            const uint32_t* h = g_h1w[(SEQ - 1) & 3];
            float s0 = 0.f, s1 = 0.f;
#pragma unroll 4
            for (int kp = 0; kp < 256; ++kp) {
                uint32_t w = __ldcg(&h[kp * BSZ + tid]);
                float lo = __bfloat162float(__ushort_as_bfloat16((unsigned short)(w & 0xFFFF)));
                float hi = __bfloat162float(__ushort_as_bfloat16((unsigned short)(w >> 16)));
                s0 += lo * Wfc[2 * kp];
                s1 += hi * Wfc[2 * kp + 1];
            }
            out[tid] = s0 + s1 + bfc[0];
        }
    }

    // ---- exit protocol: reset counters for the next graph replay ----
    __syncthreads();
    if (tid == 0) redrel(&g_done);
    if (cta == 0 && tid == 0) {
        unsigned v;
        do {
            asm volatile("ld.acquire.gpu.global.u32 %0, [%1];" : "=r"(v) : "l"(&g_done));
        } while ((int)(v - NC) < 0);
        *(volatile unsigned*)&g_c0 = 0u;
        *(volatile unsigned*)&g_c1 = 0u;
        *(volatile unsigned*)&g_done = 0u;
    }
}

// x[b][t][i] -> pair-words [t][kp][b]
__global__ void xpose_kernel(const float* __restrict__ x) {
    int idx = blockIdx.x * blockDim.x + threadIdx.x;
    if (idx < SEQ * 32 * BSZ) {
        int b  = idx & 63;
        int kp = (idx >> 6) & 31;
        int t  = idx >> 11;
        const float* xe = x + ((b * SEQ) + t) * 64 + 2 * kp;
        g_xw[idx] = packbf2(xe[0], xe[1]);
    }
}

extern "C" void kernel_launch(void* const* d_in, const int* in_sizes, int n_in,
                              void* d_out, int out_size) {
    (void)in_sizes; (void)n_in; (void)out_size;
    const float* x   = (const float*)d_in[0];
    const float* W0  = (const float*)d_in[1];
    const float* b0  = (const float*)d_in[2];
    const float* W1  = (const float*)d_in[3];
    const float* b1  = (const float*)d_in[4];
    const float* Wfc = (const float*)d_in[5];
    const float* bfc = (const float*)d_in[6];
    float* out = (float*)d_out;

    cudaFuncSetAttribute(lstm_persist,
                         cudaFuncAttributeMaxDynamicSharedMemorySize, SMEM_BYTES);

    xpose_kernel<<<(SEQ * 32 * BSZ + 255) / 256, 256>>>(x);
    lstm_persist<<<NC, NTHR, SMEM_BYTES>>>(W0, b0, W1, b1, Wfc, bfc, out);
}